// round 6
// baseline (speedup 1.0000x reference)
#include <cuda_runtime.h>
#include <cub/cub.cuh>
#include <cstdint>
#include <cstddef>

// ---------------------------------------------------------------------------
// Static scratch (no allocation allowed anywhere).
//   n = 50,000 nodes, E = 800,000, T = 26,400,000 entries (fixed shapes; caps
//   are padded).
// ---------------------------------------------------------------------------
static constexpr int    MAX_N = 65536;              // >= 50,000 nodes
static constexpr size_t MAX_E = 1u << 20;           // >= 800,000 edges
static constexpr size_t MAX_T = 27000000;           // >= 26,400,000 entries
static constexpr size_t CUB_TMP_BYTES = 64ull << 20; // DoubleBuffer path: ~MBs needed

__device__ float              g_diag[MAX_N * 16];        //   4 MB
__device__ float              g_triu[MAX_E * 16];        //  64 MB
__device__ unsigned long long g_keys_a[MAX_T];           // 216 MB  (sort ping)
__device__ unsigned long long g_keys_b[MAX_T];           // 216 MB  (sort pong)
__device__ float              g_vals_a[MAX_T];           // 108 MB
__device__ float              g_vals_b[MAX_T];           // 108 MB
__device__ unsigned char      g_cub_tmp[CUB_TMP_BYTES];  //  64 MB

// ---------------------------------------------------------------------------
// Zero the diag accumulator (graph replays re-run the atomics).
// ---------------------------------------------------------------------------
__global__ void k_zero(float* __restrict__ p, int n16)
{
    int i = blockIdx.x * blockDim.x + threadIdx.x;
    if (i < n16) p[i] = 0.0f;
}

// ---------------------------------------------------------------------------
// Kernel A: per-edge 4x4 products.
//   For all e in [0, 2E): C = A_e^T A_e, atomicAdd into g_diag[node(e)].
//   For e in [0, E):      g_triu[e] = A_e^T A_{E+e}.
// edge_index layout: (2, 2E) row-major -> ei[e] = edge_index[0,e],
//                                         ei[twoE+e] = edge_index[1,e].
// ---------------------------------------------------------------------------
__global__ void k_edge(const float* __restrict__ maps,
                       const int* __restrict__ ei,
                       int E, int twoE)
{
    int e = blockIdx.x * blockDim.x + threadIdx.x;
    if (e >= twoE) return;

    const float4* Ap = reinterpret_cast<const float4*>(maps + (size_t)e * 16);
    float Am[4][4];
#pragma unroll
    for (int r = 0; r < 4; r++) {
        float4 q = Ap[r];
        Am[r][0] = q.x; Am[r][1] = q.y; Am[r][2] = q.z; Am[r][3] = q.w;
    }

    int node = ei[e];
    float* dst = g_diag + (size_t)node * 16;
#pragma unroll
    for (int b = 0; b < 4; b++) {
#pragma unroll
        for (int c = 0; c < 4; c++) {
            float s = Am[0][b] * Am[0][c] + Am[1][b] * Am[1][c]
                    + Am[2][b] * Am[2][c] + Am[3][b] * Am[3][c];
            atomicAdd(dst + b * 4 + c, s);
        }
    }

    if (e < E) {
        const float4* Bp = reinterpret_cast<const float4*>(maps + (size_t)(E + e) * 16);
        float Bm[4][4];
#pragma unroll
        for (int r = 0; r < 4; r++) {
            float4 q = Bp[r];
            Bm[r][0] = q.x; Bm[r][1] = q.y; Bm[r][2] = q.z; Bm[r][3] = q.w;
        }
        float4* tri = reinterpret_cast<float4*>(g_triu + (size_t)e * 16);
#pragma unroll
        for (int b = 0; b < 4; b++) {
            float4 o;
            o.x = Am[0][b] * Bm[0][0] + Am[1][b] * Bm[1][0] + Am[2][b] * Bm[2][0] + Am[3][b] * Bm[3][0];
            o.y = Am[0][b] * Bm[0][1] + Am[1][b] * Bm[1][1] + Am[2][b] * Bm[2][1] + Am[3][b] * Bm[3][1];
            o.z = Am[0][b] * Bm[0][2] + Am[1][b] * Bm[1][2] + Am[2][b] * Bm[2][2] + Am[3][b] * Bm[3][2];
            o.w = Am[0][b] * Bm[0][3] + Am[1][b] * Bm[1][3] + Am[2][b] * Bm[2][3] + Am[3][b] * Bm[3][3];
            tri[b] = o;
        }
    }
}

// ---------------------------------------------------------------------------
// Kernel B: materialize (key, value) pairs in reference concatenation order:
//   [0, T0)            diag entries      (T0 = n*16)
//   [T0, T0+16E)       ij  entries: (row*4+a, col*4+b) -> -triu[e][a][b]
//   [T0+16E, T)        ji  entries: (col*4+a, row*4+b) -> -triu[e][b][a]
// key = (r << 18) | c  (r, c < 2^18). Stable radix sort == jnp.lexsort
// (ties resolved by materialization index, which matches the reference's
// concatenation order).
// ---------------------------------------------------------------------------
__global__ void k_build(const int* __restrict__ ei, int E, int twoE,
                        long long T0, long long T)
{
    long long t = (long long)blockIdx.x * blockDim.x + threadIdx.x;
    if (t >= T) return;

    unsigned int r, c;
    float v;
    if (t < T0) {
        long long i = t >> 4;
        int idx = (int)(t & 15);
        r = (unsigned int)(i * 4 + (idx >> 2));
        c = (unsigned int)(i * 4 + (idx & 3));
        v = g_diag[t];
    } else {
        long long u = t - T0;
        long long ijN = (long long)E * 16;
        if (u < ijN) {
            int e = (int)(u >> 4);
            int idx = (int)(u & 15);
            int a = idx >> 2, b = idx & 3;
            r = (unsigned int)(ei[e] * 4 + a);
            c = (unsigned int)(ei[twoE + e] * 4 + b);
            v = -g_triu[(size_t)e * 16 + idx];
        } else {
            u -= ijN;
            int e = (int)(u >> 4);
            int idx = (int)(u & 15);
            int a = idx >> 2, b = idx & 3;
            r = (unsigned int)(ei[twoE + e] * 4 + a);
            c = (unsigned int)(ei[e] * 4 + b);
            v = -g_triu[(size_t)e * 16 + b * 4 + a];
        }
    }
    g_keys_a[t] = ((unsigned long long)r << 18) | (unsigned long long)c;
    g_vals_a[t] = v;
}

// ---------------------------------------------------------------------------
// Kernel C: unpack sorted keys into output layout [rows | cols | values].
// Sorted buffers are passed as args (CUB DoubleBuffer selector decides which
// physical buffer holds the result; resolved on host at capture time).
// ---------------------------------------------------------------------------
__global__ void k_emit(float* __restrict__ out,
                       const unsigned long long* __restrict__ keys,
                       const float* __restrict__ vals,
                       long long T)
{
    long long t = (long long)blockIdx.x * blockDim.x + threadIdx.x;
    if (t >= T) return;
    unsigned long long k = keys[t];
    out[t]         = (float)(unsigned int)(k >> 18);
    out[T + t]     = (float)(unsigned int)(k & 0x3FFFFu);
    out[2 * T + t] = vals[t];
}

// ---------------------------------------------------------------------------
// Launch (graph-capturable: kernel launches + CUB stream-ordered launches).
// ---------------------------------------------------------------------------
extern "C" void kernel_launch(void* const* d_in, const int* in_sizes, int n_in,
                              void* d_out, int out_size)
{
    const float* maps = (const float*)d_in[0];
    const int*   ei   = (const int*)d_in[1];

    const long long mapsN = (long long)in_sizes[0];  // 2E * 16
    const int twoE = (int)(mapsN / 16);
    const int E = twoE / 2;
    const long long T = (long long)out_size / 3;     // total COO entries
    const int n = (int)((T - (long long)E * 32) / 16);
    const long long T0 = (long long)n * 16;

    // Resolve device-global addresses (host API, capture-safe).
    void *diag_p, *ka_p, *kb_p, *va_p, *vb_p, *tmp_p;
    cudaGetSymbolAddress(&diag_p, g_diag);
    cudaGetSymbolAddress(&ka_p,   g_keys_a);
    cudaGetSymbolAddress(&kb_p,   g_keys_b);
    cudaGetSymbolAddress(&va_p,   g_vals_a);
    cudaGetSymbolAddress(&vb_p,   g_vals_b);
    cudaGetSymbolAddress(&tmp_p,  g_cub_tmp);

    const int tB = 256;

    // Zero diag accumulator via kernel (memset node avoided for capture safety).
    k_zero<<<(n * 16 + tB - 1) / tB, tB>>>((float*)diag_p, n * 16);

    k_edge<<<(twoE + tB - 1) / tB, tB>>>(maps, ei, E, twoE);

    const int gridT = (int)((T + tB - 1) / tB);
    k_build<<<gridT, tB>>>(ei, E, twoE, T0, T);

    // Stable radix sort of (36-bit key, f32 payload) pairs.
    // DoubleBuffer overload: temp storage holds only histograms/lookback state
    // (a few MB), NOT item-sized buffers. Selector is updated on the host
    // during this call (pass count is shape-determined), so Current() is valid
    // and deterministic at capture time.
    cub::DoubleBuffer<unsigned long long> dk((unsigned long long*)ka_p,
                                             (unsigned long long*)kb_p);
    cub::DoubleBuffer<float>              dv((float*)va_p, (float*)vb_p);

    size_t tmp_bytes = 0;
    cub::DeviceRadixSort::SortPairs(nullptr, tmp_bytes, dk, dv, (int)T, 0, 36);
    // tmp_bytes for the DoubleBuffer path is far below CUB_TMP_BYTES (64 MB);
    // pass the full static buffer size so the call never under-provisions.
    tmp_bytes = CUB_TMP_BYTES;
    cub::DeviceRadixSort::SortPairs(tmp_p, tmp_bytes, dk, dv, (int)T, 0, 36);

    k_emit<<<gridT, tB>>>((float*)d_out, dk.Current(), dv.Current(), T);
}

// round 8
// speedup vs baseline: 4.1692x; 4.1692x over previous
#include <cuda_runtime.h>
#include <cub/cub.cuh>
#include <cstdint>
#include <cstddef>

// ---------------------------------------------------------------------------
// Shapes: n = 50,000 nodes, E = 800,000 (2E = 1.6M maps), T = 26.4M entries.
// Items (per-node incident list): n + 2E = 1.65M.
// ---------------------------------------------------------------------------
static constexpr int    MAX_N = 65536;
static constexpr size_t MAX_E = 1u << 20;            // >= 800,000
static constexpr size_t MAX_I = 1u << 21;            // >= n + 2E = 1.65M
static constexpr size_t SCAN_TMP_BYTES = 4u << 20;

static constexpr int SORT_CAP = 256;   // max items per node (Poisson(32) tail: ~0)

__device__ float              g_diag[MAX_N * 16];       //  4 MB
__device__ float              g_triu[MAX_E * 16];       // 64 MB
__device__ unsigned long long g_items[MAX_I];           // 16 MB  (bucketed keys)
__device__ int                g_cnt[MAX_N + 1];
__device__ int                g_off[MAX_N + 1];
__device__ int                g_cur[MAX_N];
__device__ unsigned char      g_scan_tmp[SCAN_TMP_BYTES];

// ---------------------------------------------------------------------------
// Zero accumulators (graph replays re-run atomics).
// ---------------------------------------------------------------------------
__global__ void k_init(int n)
{
    int i = blockIdx.x * blockDim.x + threadIdx.x;
    int n16 = n * 16;
    if (i < n16) g_diag[i] = 0.0f;
    if (i <= n)  g_cnt[i] = 0;
    if (i < n)   g_cur[i] = 0;
}

// ---------------------------------------------------------------------------
// Per-edge 4x4 products + incidence counts.
//   e in [0,2E): C = A_e^T A_e atomically added into g_diag[ei[e]].
//   e in [0,E):  g_triu[e] = A_e^T A_{E+e};  count ij at ei[e], ji at ei[2E+e].
// ---------------------------------------------------------------------------
__global__ void k_edge(const float* __restrict__ maps,
                       const int* __restrict__ ei,
                       int E, int twoE)
{
    int e = blockIdx.x * blockDim.x + threadIdx.x;
    if (e >= twoE) return;

    const float4* Ap = reinterpret_cast<const float4*>(maps + (size_t)e * 16);
    float Am[4][4];
#pragma unroll
    for (int r = 0; r < 4; r++) {
        float4 q = Ap[r];
        Am[r][0] = q.x; Am[r][1] = q.y; Am[r][2] = q.z; Am[r][3] = q.w;
    }

    int node = ei[e];
    float* dst = g_diag + (size_t)node * 16;
#pragma unroll
    for (int b = 0; b < 4; b++) {
#pragma unroll
        for (int c = 0; c < 4; c++) {
            float s = Am[0][b] * Am[0][c] + Am[1][b] * Am[1][c]
                    + Am[2][b] * Am[2][c] + Am[3][b] * Am[3][c];
            atomicAdd(dst + b * 4 + c, s);
        }
    }

    if (e < E) {
        const float4* Bp = reinterpret_cast<const float4*>(maps + (size_t)(E + e) * 16);
        float Bm[4][4];
#pragma unroll
        for (int r = 0; r < 4; r++) {
            float4 q = Bp[r];
            Bm[r][0] = q.x; Bm[r][1] = q.y; Bm[r][2] = q.z; Bm[r][3] = q.w;
        }
        float4* tri = reinterpret_cast<float4*>(g_triu + (size_t)e * 16);
#pragma unroll
        for (int b = 0; b < 4; b++) {
            float4 o;
            o.x = Am[0][b] * Bm[0][0] + Am[1][b] * Bm[1][0] + Am[2][b] * Bm[2][0] + Am[3][b] * Bm[3][0];
            o.y = Am[0][b] * Bm[0][1] + Am[1][b] * Bm[1][1] + Am[2][b] * Bm[2][1] + Am[3][b] * Bm[3][1];
            o.z = Am[0][b] * Bm[0][2] + Am[1][b] * Bm[1][2] + Am[2][b] * Bm[2][2] + Am[3][b] * Bm[3][2];
            o.w = Am[0][b] * Bm[0][3] + Am[1][b] * Bm[1][3] + Am[2][b] * Bm[2][3] + Am[3][b] * Bm[3][3];
            tri[b] = o;
        }
        // incidence counts for the per-node item lists
        atomicAdd(&g_cnt[node], 1);              // ij item at row node
        atomicAdd(&g_cnt[ei[twoE + e]], 1);      // ji item at col node
    }
}

// ---------------------------------------------------------------------------
// Count diag items (1 per node) — folded in here to keep k_edge tight.
// ---------------------------------------------------------------------------
__global__ void k_cnt_diag(int n)
{
    int u = blockIdx.x * blockDim.x + threadIdx.x;
    if (u < n) atomicAdd(&g_cnt[u], 1);
}

// ---------------------------------------------------------------------------
// Scatter items into per-node buckets.
//   key = (col_node << 22) | tiekey
//   tiekey: 0 = diag, 1+e = ij edge e, 1+E+e = ji edge e.
// Bucket order is arbitrary (atomics); keys are unique within a node, so the
// per-node sort is fully deterministic.
// ---------------------------------------------------------------------------
__global__ void k_scatter(const int* __restrict__ ei, int n, int E, int twoE)
{
    int t = blockIdx.x * blockDim.x + threadIdx.x;
    if (t < n) {
        int u = t;
        int pos = g_off[u] + atomicAdd(&g_cur[u], 1);
        g_items[pos] = ((unsigned long long)u << 22);           // diag, tie=0
    } else if (t < n + E) {
        int e = t - n;
        int u  = ei[e];
        int v  = ei[twoE + e];
        int p1 = g_off[u] + atomicAdd(&g_cur[u], 1);
        g_items[p1] = ((unsigned long long)v << 22) | (unsigned long long)(1 + e);
        int p2 = g_off[v] + atomicAdd(&g_cur[v], 1);
        g_items[p2] = ((unsigned long long)u << 22) | (unsigned long long)(1 + E + e);
    }
}

// ---------------------------------------------------------------------------
// Fused per-node sort + expansion + emit.  One warp per node.
//   - bitonic sort of the node's item list (padded to pow2 <= 256) in SMEM
//   - equal-col-node runs expanded column-major (reference tie semantics)
//   - output written directly: rows / cols / vals, fully coalesced.
// ---------------------------------------------------------------------------
static constexpr int SE_WARPS = 8;

__global__ __launch_bounds__(SE_WARPS * 32)
void k_sort_emit(float* __restrict__ out, int n, int E, long long T)
{
    __shared__ unsigned long long skey[SE_WARPS][SORT_CAP];
    __shared__ short sstart[SE_WARPS][SORT_CAP];
    __shared__ short slen[SE_WARPS][SORT_CAP];

    int w    = threadIdx.x >> 5;
    int lane = threadIdx.x & 31;
    int u    = blockIdx.x * SE_WARPS + w;
    if (u >= n) return;

    int beg = g_off[u];
    int m   = g_off[u + 1] - beg;            // >= 1 (diag always present)

    int P = 32;
    while (P < m) P <<= 1;                   // pow2 pad, <= SORT_CAP

    for (int i = lane; i < P; i += 32)
        skey[w][i] = (i < m) ? g_items[beg + i] : ~0ull;
    __syncwarp();

    // bitonic sort over P elements
    for (int k = 2; k <= P; k <<= 1) {
        for (int j = k >> 1; j > 0; j >>= 1) {
            for (int i = lane; i < P; i += 32) {
                int l = i ^ j;
                if (l > i) {
                    unsigned long long a = skey[w][i];
                    unsigned long long b = skey[w][l];
                    bool up = ((i & k) == 0);
                    if ((a > b) == up) { skey[w][i] = b; skey[w][l] = a; }
                }
            }
            __syncwarp();
        }
    }

    // equal-col-node run extents (runs are tiny; per-item walk is fine)
    for (int p = lane; p < m; p += 32) {
        unsigned int cn = (unsigned int)(skey[w][p] >> 22);
        int s = p;
        while (s > 0 && (unsigned int)(skey[w][s - 1] >> 22) == cn) s--;
        int t = p;
        while (t + 1 < m && (unsigned int)(skey[w][t + 1] >> 22) == cn) t++;
        sstart[w][p] = (short)s;
        slen[w][p]   = (short)(t - s + 1);
    }
    __syncwarp();

    long long base = (long long)beg * 16;
    int m4 = m * 4;
    float* rows = out;
    float* cols = out + T;
    float* vals = out + 2 * T;

#pragma unroll
    for (int a = 0; a < 4; a++) {
        float rowv = (float)(u * 4 + a);
        long long rbase = base + (long long)a * m4;
        for (int i = lane; i < m4; i += 32) {
            int p0 = i >> 2;
            int s  = sstart[w][p0];
            int L  = slen[w][p0];
            int p, b;
            if (L == 1) { p = p0; b = i & 3; }
            else        { int j = i - 4 * s; b = j / L; p = s + j % L; }

            unsigned long long k = skey[w][p];
            unsigned int tie = (unsigned int)(k & 0x3FFFFFu);
            unsigned int cn  = (unsigned int)(k >> 22);

            float v;
            if (tie == 0)
                v = g_diag[(size_t)u * 16 + a * 4 + b];
            else if (tie <= (unsigned int)E)
                v = -g_triu[(size_t)(tie - 1) * 16 + a * 4 + b];
            else
                v = -g_triu[(size_t)(tie - 1 - E) * 16 + b * 4 + a];

            long long o = rbase + i;
            rows[o] = rowv;
            cols[o] = (float)(cn * 4 + b);
            vals[o] = v;
        }
    }
}

// ---------------------------------------------------------------------------
// Launch (kernel launches + CUB scan only — graph-capturable).
// ---------------------------------------------------------------------------
extern "C" void kernel_launch(void* const* d_in, const int* in_sizes, int n_in,
                              void* d_out, int out_size)
{
    const float* maps = (const float*)d_in[0];
    const int*   ei   = (const int*)d_in[1];

    const long long mapsN = (long long)in_sizes[0];   // 2E * 16
    const int twoE = (int)(mapsN / 16);
    const int E = twoE / 2;
    const long long T = (long long)out_size / 3;
    const int n = (int)((T - (long long)E * 32) / 16);

    void *cnt_p, *off_p, *tmp_p;
    cudaGetSymbolAddress(&cnt_p, g_cnt);
    cudaGetSymbolAddress(&off_p, g_off);
    cudaGetSymbolAddress(&tmp_p, g_scan_tmp);

    const int tB = 256;

    k_init<<<(n * 16 + tB - 1) / tB, tB>>>(n);
    k_cnt_diag<<<(n + tB - 1) / tB, tB>>>(n);
    k_edge<<<(twoE + tB - 1) / tB, tB>>>(maps, ei, E, twoE);

    // offsets = exclusive_sum(counts) over n+1 slots (off[n] = total items)
    size_t tmp_bytes = SCAN_TMP_BYTES;
    cub::DeviceScan::ExclusiveSum(tmp_p, tmp_bytes,
                                  (const int*)cnt_p, (int*)off_p, n + 1);

    k_scatter<<<(n + E + tB - 1) / tB, tB>>>(ei, n, E, twoE);

    int seBlocks = (n + SE_WARPS - 1) / SE_WARPS;
    k_sort_emit<<<seBlocks, SE_WARPS * 32>>>((float*)d_out, n, E, T);
}

// round 9
// speedup vs baseline: 4.4517x; 1.0678x over previous
#include <cuda_runtime.h>
#include <cub/cub.cuh>
#include <cstdint>
#include <cstddef>

// ---------------------------------------------------------------------------
// Shapes: n = 50,000 nodes, E = 800,000 (2E = 1.6M maps), T = 26.4M entries.
// Items (per-node incident list): n + 2E = 1.65M.
// ---------------------------------------------------------------------------
static constexpr int    MAX_N = 65536;
static constexpr size_t MAX_E = 1u << 20;            // >= 800,000
static constexpr size_t MAX_I = 1u << 21;            // >= n + 2E = 1.65M
static constexpr size_t SCAN_TMP_BYTES = 4u << 20;

static constexpr int SORT_CAP = 256;   // max items per node (Poisson(33) tail: ~0)

__device__ float              g_diag[MAX_N * 16];       //  4 MB
__device__ float              g_triu[MAX_E * 16];       // 64 MB  (A^T B, row-major)
__device__ float              g_triuT[MAX_E * 16];      // 64 MB  (transposed copy)
__device__ unsigned long long g_items[MAX_I];           // 16 MB  (bucketed keys)
__device__ int                g_cnt[MAX_N + 1];
__device__ int                g_off[MAX_N + 1];
__device__ int                g_cur[MAX_N];
__device__ unsigned char      g_scan_tmp[SCAN_TMP_BYTES];

// ---------------------------------------------------------------------------
// Zero/seed accumulators (graph replays re-run atomics).
// cnt[u] starts at 1: the diag item of every node.
// ---------------------------------------------------------------------------
__global__ void k_init(int n)
{
    int i = blockIdx.x * blockDim.x + threadIdx.x;
    int n16 = n * 16;
    if (i < n16) g_diag[i] = 0.0f;
    if (i < n)  { g_cnt[i] = 1; g_cur[i] = 0; }
    if (i == n)  g_cnt[n] = 0;
}

// ---------------------------------------------------------------------------
// Per-edge 4x4 products + incidence counts.
//   e in [0,2E): C = A_e^T A_e atomically added into g_diag[ei[e]].
//   e in [0,E):  g_triu[e] = A_e^T A_{E+e} (+ transposed copy);
//                count ij at ei[e], ji at ei[2E+e].
// ---------------------------------------------------------------------------
__global__ void k_edge(const float* __restrict__ maps,
                       const int* __restrict__ ei,
                       int E, int twoE)
{
    int e = blockIdx.x * blockDim.x + threadIdx.x;
    if (e >= twoE) return;

    const float4* Ap = reinterpret_cast<const float4*>(maps + (size_t)e * 16);
    float Am[4][4];
#pragma unroll
    for (int r = 0; r < 4; r++) {
        float4 q = Ap[r];
        Am[r][0] = q.x; Am[r][1] = q.y; Am[r][2] = q.z; Am[r][3] = q.w;
    }

    int node = ei[e];
    float* dst = g_diag + (size_t)node * 16;
#pragma unroll
    for (int b = 0; b < 4; b++) {
#pragma unroll
        for (int c = 0; c < 4; c++) {
            float s = Am[0][b] * Am[0][c] + Am[1][b] * Am[1][c]
                    + Am[2][b] * Am[2][c] + Am[3][b] * Am[3][c];
            atomicAdd(dst + b * 4 + c, s);
        }
    }

    if (e < E) {
        const float4* Bp = reinterpret_cast<const float4*>(maps + (size_t)(E + e) * 16);
        float Bm[4][4];
#pragma unroll
        for (int r = 0; r < 4; r++) {
            float4 q = Bp[r];
            Bm[r][0] = q.x; Bm[r][1] = q.y; Bm[r][2] = q.z; Bm[r][3] = q.w;
        }
        float C[4][4];
#pragma unroll
        for (int b = 0; b < 4; b++)
#pragma unroll
            for (int c = 0; c < 4; c++)
                C[b][c] = Am[0][b] * Bm[0][c] + Am[1][b] * Bm[1][c]
                        + Am[2][b] * Bm[2][c] + Am[3][b] * Bm[3][c];

        float4* tri  = reinterpret_cast<float4*>(g_triu  + (size_t)e * 16);
        float4* triT = reinterpret_cast<float4*>(g_triuT + (size_t)e * 16);
#pragma unroll
        for (int b = 0; b < 4; b++) {
            tri [b] = make_float4(C[b][0], C[b][1], C[b][2], C[b][3]);
            triT[b] = make_float4(C[0][b], C[1][b], C[2][b], C[3][b]);
        }
        // incidence counts for the per-node item lists
        atomicAdd(&g_cnt[node], 1);              // ij item at row node
        atomicAdd(&g_cnt[ei[twoE + e]], 1);      // ji item at col node
    }
}

// ---------------------------------------------------------------------------
// Scatter items into per-node buckets.
//   key = (col_node << 22) | tiekey
//   tiekey: 0 = diag, 1+e = ij edge e, 1+E+e = ji edge e.
// Bucket order is arbitrary (atomics); keys are unique within a node, so the
// per-node sort is fully deterministic and reproduces the reference's stable
// lexsort tie-breaking (tiekey == concatenation order).
// ---------------------------------------------------------------------------
__global__ void k_scatter(const int* __restrict__ ei, int n, int E, int twoE)
{
    int t = blockIdx.x * blockDim.x + threadIdx.x;
    if (t < n) {
        int u = t;
        int pos = g_off[u] + atomicAdd(&g_cur[u], 1);
        g_items[pos] = ((unsigned long long)u << 22);           // diag, tie=0
    } else if (t < n + E) {
        int e = t - n;
        int u  = ei[e];
        int v  = ei[twoE + e];
        int p1 = g_off[u] + atomicAdd(&g_cur[u], 1);
        g_items[p1] = ((unsigned long long)v << 22) | (unsigned long long)(1 + e);
        int p2 = g_off[v] + atomicAdd(&g_cur[v], 1);
        g_items[p2] = ((unsigned long long)u << 22) | (unsigned long long)(1 + E + e);
    }
}

// ---------------------------------------------------------------------------
// Fused per-node sort + expansion + emit.  One warp per node.
//   - bitonic sort of the node's item list (pow2-padded) in SMEM
//   - FAST PATH (no equal-col-node runs, ~99% of nodes): one item per lane,
//     float4 value gather + float4 stores to rows/cols/vals (STG.128).
//   - TIE PATH: scalar expansion with column-major run interleave
//     (reference tie semantics), run extents computed inline.
// Diag item offset = 1 before any edge tie (tie=0 sorts first) — handled by
// key order, not special-cased here.
// ---------------------------------------------------------------------------
static constexpr int SE_WARPS = 8;

__global__ __launch_bounds__(SE_WARPS * 32)
void k_sort_emit(float* __restrict__ out, int n, int E, long long T)
{
    __shared__ unsigned long long skey[SE_WARPS][SORT_CAP];

    int w    = threadIdx.x >> 5;
    int lane = threadIdx.x & 31;
    int u    = blockIdx.x * SE_WARPS + w;
    if (u >= n) return;

    int beg = g_off[u];
    int m   = g_off[u + 1] - beg;            // >= 1 (diag always present)

    int P = 32;
    while (P < m) P <<= 1;                   // pow2 pad, <= SORT_CAP

    for (int i = lane; i < P; i += 32)
        skey[w][i] = (i < m) ? g_items[beg + i] : ~0ull;
    __syncwarp();

    // bitonic sort over P elements
    for (int k = 2; k <= P; k <<= 1) {
        for (int j = k >> 1; j > 0; j >>= 1) {
            for (int i = lane; i < P; i += 32) {
                int l = i ^ j;
                if (l > i) {
                    unsigned long long a = skey[w][i];
                    unsigned long long b = skey[w][l];
                    bool up = ((i & k) == 0);
                    if ((a > b) == up) { skey[w][i] = b; skey[w][l] = a; }
                }
            }
            __syncwarp();
        }
    }

    // any equal-col-node runs in this node?
    bool mytie = false;
    for (int p = lane; p < m; p += 32)
        if (p > 0 && (skey[w][p] >> 22) == (skey[w][p - 1] >> 22)) mytie = true;
    bool has_tie = __any_sync(0xffffffffu, mytie);

    long long base = (long long)beg * 16;    // element offset of this node's block
    float* rows = out;
    float* cols = out + T;
    float* vals = out + 2 * T;

    if (!has_tie) {
        // -------- fast path: one item per lane, float4 everywhere --------
#pragma unroll
        for (int a = 0; a < 4; a++) {
            float rowv = (float)(u * 4 + a);
            long long rbase = base + (long long)a * (m * 4);   // multiple of 4
            for (int p = lane; p < m; p += 32) {
                unsigned long long k = skey[w][p];
                unsigned int tie = (unsigned int)(k & 0x3FFFFFu);
                unsigned int cn  = (unsigned int)(k >> 22);

                float4 v4;
                if (tie == 0) {
                    v4 = *reinterpret_cast<const float4*>(g_diag + (size_t)u * 16 + a * 4);
                } else if (tie <= (unsigned int)E) {
                    float4 t4 = *reinterpret_cast<const float4*>(g_triu + (size_t)(tie - 1) * 16 + a * 4);
                    v4 = make_float4(-t4.x, -t4.y, -t4.z, -t4.w);
                } else {
                    float4 t4 = *reinterpret_cast<const float4*>(g_triuT + (size_t)(tie - 1 - E) * 16 + a * 4);
                    v4 = make_float4(-t4.x, -t4.y, -t4.z, -t4.w);
                }

                long long o4 = (rbase >> 2) + p;               // float4 index
                float c0 = (float)(cn * 4);
                reinterpret_cast<float4*>(rows)[o4] = make_float4(rowv, rowv, rowv, rowv);
                reinterpret_cast<float4*>(cols)[o4] = make_float4(c0, c0 + 1.0f, c0 + 2.0f, c0 + 3.0f);
                reinterpret_cast<float4*>(vals)[o4] = v4;
            }
        }
    } else {
        // -------- tie path: scalar, column-major run interleave --------
        int m4 = m * 4;
#pragma unroll
        for (int a = 0; a < 4; a++) {
            float rowv = (float)(u * 4 + a);
            long long rbase = base + (long long)a * m4;
            for (int i = lane; i < m4; i += 32) {
                int p0 = i >> 2;
                unsigned int cn0 = (unsigned int)(skey[w][p0] >> 22);
                int s = p0, t = p0;
                while (s > 0 && (unsigned int)(skey[w][s - 1] >> 22) == cn0) s--;
                while (t + 1 < m && (unsigned int)(skey[w][t + 1] >> 22) == cn0) t++;
                int L = t - s + 1;
                int p, b;
                if (L == 1) { p = p0; b = i & 3; }
                else        { int j = i - 4 * s; b = j / L; p = s + j % L; }

                unsigned long long k = skey[w][p];
                unsigned int tie = (unsigned int)(k & 0x3FFFFFu);
                unsigned int cn  = (unsigned int)(k >> 22);

                float v;
                if (tie == 0)
                    v = g_diag[(size_t)u * 16 + a * 4 + b];
                else if (tie <= (unsigned int)E)
                    v = -g_triu[(size_t)(tie - 1) * 16 + a * 4 + b];
                else
                    v = -g_triu[(size_t)(tie - 1 - E) * 16 + b * 4 + a];

                long long o = rbase + i;
                rows[o] = rowv;
                cols[o] = (float)(cn * 4 + b);
                vals[o] = v;
            }
        }
    }
}

// ---------------------------------------------------------------------------
// Launch (kernel launches + CUB scan only — graph-capturable).
// ---------------------------------------------------------------------------
extern "C" void kernel_launch(void* const* d_in, const int* in_sizes, int n_in,
                              void* d_out, int out_size)
{
    const float* maps = (const float*)d_in[0];
    const int*   ei   = (const int*)d_in[1];

    const long long mapsN = (long long)in_sizes[0];   // 2E * 16
    const int twoE = (int)(mapsN / 16);
    const int E = twoE / 2;
    const long long T = (long long)out_size / 3;
    const int n = (int)((T - (long long)E * 32) / 16);

    void *cnt_p, *off_p, *tmp_p;
    cudaGetSymbolAddress(&cnt_p, g_cnt);
    cudaGetSymbolAddress(&off_p, g_off);
    cudaGetSymbolAddress(&tmp_p, g_scan_tmp);

    const int tB = 256;

    k_init<<<(n * 16 + tB - 1) / tB, tB>>>(n);
    k_edge<<<(twoE + tB - 1) / tB, tB>>>(maps, ei, E, twoE);

    // offsets = exclusive_sum(counts) over n+1 slots (off[n] = total items)
    size_t tmp_bytes = SCAN_TMP_BYTES;
    cub::DeviceScan::ExclusiveSum(tmp_p, tmp_bytes,
                                  (const int*)cnt_p, (int*)off_p, n + 1);

    k_scatter<<<(n + E + tB - 1) / tB, tB>>>(ei, n, E, twoE);

    int seBlocks = (n + SE_WARPS - 1) / SE_WARPS;
    k_sort_emit<<<seBlocks, SE_WARPS * 32>>>((float*)d_out, n, E, T);
}

// round 14
// speedup vs baseline: 5.7749x; 1.2972x over previous
#include <cuda_runtime.h>
#include <cub/cub.cuh>
#include <cstdint>
#include <cstddef>

// ---------------------------------------------------------------------------
// Shapes: n = 50,000 nodes, E = 800,000 (2E = 1.6M maps), T = 26.4M entries.
// Items (per-node incident list): n + 2E = 1.65M.
// ---------------------------------------------------------------------------
static constexpr int    MAX_N = 65536;
static constexpr size_t MAX_E = 1u << 20;            // >= 800,000
static constexpr size_t MAX_I = 1u << 21;            // >= n + 2E = 1.65M
static constexpr size_t SCAN_TMP_BYTES = 4u << 20;

static constexpr int SORT_CAP = 256;   // max items per node (Poisson(33) tail: ~0)

__device__ float              g_diag[MAX_N * 16];       //  4 MB
__device__ float              g_triu[MAX_E * 16];       // 64 MB  (A^T B, row-major)
__device__ unsigned long long g_items[MAX_I];           // 16 MB  (bucketed keys)
__device__ int                g_cnt[MAX_N + 1];
__device__ int                g_off[MAX_N + 1];
__device__ int                g_cur[MAX_N];
__device__ unsigned char      g_scan_tmp[SCAN_TMP_BYTES];

// ---------------------------------------------------------------------------
// Zero/seed accumulators (graph replays re-run atomics).
// cnt[u] starts at 1: the diag item of every node.
// ---------------------------------------------------------------------------
__global__ void k_init(int n)
{
    int i = blockIdx.x * blockDim.x + threadIdx.x;
    int n16 = n * 16;
    if (i < n16) g_diag[i] = 0.0f;
    if (i < n)  { g_cnt[i] = 1; g_cur[i] = 0; }
    if (i == n)  g_cnt[n] = 0;
}

// ---------------------------------------------------------------------------
// Per-edge 4x4 products + incidence counts.
//   e in [0,2E): S = A_e^T A_e atomically added into g_diag[ei[e]] (vec4 RED).
//   e in [0,E):  g_triu[e] = A_e^T A_{E+e}; count ij at ei[e], ji at ei[2E+e].
// ---------------------------------------------------------------------------
__global__ void k_edge(const float* __restrict__ maps,
                       const int* __restrict__ ei,
                       int E, int twoE)
{
    int e = blockIdx.x * blockDim.x + threadIdx.x;
    if (e >= twoE) return;

    const float4* Ap = reinterpret_cast<const float4*>(maps + (size_t)e * 16);
    float Am[4][4];
#pragma unroll
    for (int r = 0; r < 4; r++) {
        float4 q = Ap[r];
        Am[r][0] = q.x; Am[r][1] = q.y; Am[r][2] = q.z; Am[r][3] = q.w;
    }

    int node = ei[e];
    float* dst = g_diag + (size_t)node * 16;
#pragma unroll
    for (int b = 0; b < 4; b++) {
        float s0 = Am[0][b] * Am[0][0] + Am[1][b] * Am[1][0] + Am[2][b] * Am[2][0] + Am[3][b] * Am[3][0];
        float s1 = Am[0][b] * Am[0][1] + Am[1][b] * Am[1][1] + Am[2][b] * Am[2][1] + Am[3][b] * Am[3][1];
        float s2 = Am[0][b] * Am[0][2] + Am[1][b] * Am[1][2] + Am[2][b] * Am[2][2] + Am[3][b] * Am[3][2];
        float s3 = Am[0][b] * Am[0][3] + Am[1][b] * Am[1][3] + Am[2][b] * Am[2][3] + Am[3][b] * Am[3][3];
#if defined(__CUDA_ARCH__) && (__CUDA_ARCH__ >= 900)
        atomicAdd(reinterpret_cast<float4*>(dst) + b, make_float4(s0, s1, s2, s3));
#else
        atomicAdd(dst + b * 4 + 0, s0);
        atomicAdd(dst + b * 4 + 1, s1);
        atomicAdd(dst + b * 4 + 2, s2);
        atomicAdd(dst + b * 4 + 3, s3);
#endif
    }

    if (e < E) {
        const float4* Bp = reinterpret_cast<const float4*>(maps + (size_t)(E + e) * 16);
        float Bm[4][4];
#pragma unroll
        for (int r = 0; r < 4; r++) {
            float4 q = Bp[r];
            Bm[r][0] = q.x; Bm[r][1] = q.y; Bm[r][2] = q.z; Bm[r][3] = q.w;
        }
        float4* tri = reinterpret_cast<float4*>(g_triu + (size_t)e * 16);
#pragma unroll
        for (int b = 0; b < 4; b++) {
            float4 o;
            o.x = Am[0][b] * Bm[0][0] + Am[1][b] * Bm[1][0] + Am[2][b] * Bm[2][0] + Am[3][b] * Bm[3][0];
            o.y = Am[0][b] * Bm[0][1] + Am[1][b] * Bm[1][1] + Am[2][b] * Bm[2][1] + Am[3][b] * Bm[3][1];
            o.z = Am[0][b] * Bm[0][2] + Am[1][b] * Bm[1][2] + Am[2][b] * Bm[2][2] + Am[3][b] * Bm[3][2];
            o.w = Am[0][b] * Bm[0][3] + Am[1][b] * Bm[1][3] + Am[2][b] * Bm[2][3] + Am[3][b] * Bm[3][3];
            tri[b] = o;
        }
        atomicAdd(&g_cnt[node], 1);              // ij item at row node
        atomicAdd(&g_cnt[ei[twoE + e]], 1);      // ji item at col node
    }
}

// ---------------------------------------------------------------------------
// Scatter items into per-node buckets.
//   key = (col_node << 22) | tiekey
//   tiekey: 0 = diag, 1+e = ij edge e, 1+E+e = ji edge e.
// Bucket order is arbitrary (atomics); keys are unique within a node, so the
// per-node sort is fully deterministic and reproduces the reference's stable
// lexsort tie-breaking (tiekey == concatenation order).
// ---------------------------------------------------------------------------
__global__ void k_scatter(const int* __restrict__ ei, int n, int E, int twoE)
{
    int t = blockIdx.x * blockDim.x + threadIdx.x;
    if (t < n) {
        int u = t;
        int pos = g_off[u] + atomicAdd(&g_cur[u], 1);
        g_items[pos] = ((unsigned long long)u << 22);           // diag, tie=0
    } else if (t < n + E) {
        int e = t - n;
        int u  = ei[e];
        int v  = ei[twoE + e];
        int p1 = g_off[u] + atomicAdd(&g_cur[u], 1);
        g_items[p1] = ((unsigned long long)v << 22) | (unsigned long long)(1 + e);
        int p2 = g_off[v] + atomicAdd(&g_cur[v], 1);
        g_items[p2] = ((unsigned long long)u << 22) | (unsigned long long)(1 + E + e);
    }
}

// ---------------------------------------------------------------------------
// Fused per-node sort + expansion + emit.  One warp per node.
//   - bitonic sort of the node's item list (pow2-padded) in SMEM
//   - FAST PATH (no equal-col-node runs, ~99% of nodes): ITEM-MAJOR — each
//     lane owns one item, loads its full 64 B value block ONCE (contiguous
//     float4 x4), register-transposes for ji items, then writes all 12
//     output float4s (rows/cols/vals x 4 a-rows). Coalesced per a.
//   - TIE PATH: scalar expansion with column-major run interleave
//     (reference tie semantics), transposed indexing into g_triu for ji.
// ---------------------------------------------------------------------------
static constexpr int SE_WARPS = 8;

__global__ __launch_bounds__(SE_WARPS * 32)
void k_sort_emit(float* __restrict__ out, int n, int E, long long T)
{
    __shared__ unsigned long long skey[SE_WARPS][SORT_CAP];

    int w    = threadIdx.x >> 5;
    int lane = threadIdx.x & 31;
    int u    = blockIdx.x * SE_WARPS + w;
    if (u >= n) return;

    int beg = g_off[u];
    int m   = g_off[u + 1] - beg;            // >= 1 (diag always present)

    int P = 32;
    while (P < m) P <<= 1;                   // pow2 pad, <= SORT_CAP

    for (int i = lane; i < P; i += 32)
        skey[w][i] = (i < m) ? g_items[beg + i] : ~0ull;
    __syncwarp();

    // bitonic sort over P elements
    for (int k = 2; k <= P; k <<= 1) {
        for (int j = k >> 1; j > 0; j >>= 1) {
            for (int i = lane; i < P; i += 32) {
                int l = i ^ j;
                if (l > i) {
                    unsigned long long a = skey[w][i];
                    unsigned long long b = skey[w][l];
                    bool up = ((i & k) == 0);
                    if ((a > b) == up) { skey[w][i] = b; skey[w][l] = a; }
                }
            }
            __syncwarp();
        }
    }

    // any equal-col-node runs in this node?
    bool mytie = false;
    for (int p = lane; p < m; p += 32)
        if (p > 0 && (skey[w][p] >> 22) == (skey[w][p - 1] >> 22)) mytie = true;
    bool has_tie = __any_sync(0xffffffffu, mytie);

    long long base = (long long)beg * 16;    // element offset of this node's block
    float* rows = out;
    float* cols = out + T;
    float* vals = out + 2 * T;

    if (!has_tie) {
        // -------- fast path: item-major, one 64 B value load per item --------
        long long b4 = base >> 2;            // float4 index of node block start
        float4* rows4 = reinterpret_cast<float4*>(rows);
        float4* cols4 = reinterpret_cast<float4*>(cols);
        float4* vals4 = reinterpret_cast<float4*>(vals);

        for (int p = lane; p < m; p += 32) {
            unsigned long long k = skey[w][p];
            unsigned int tie = (unsigned int)(k & 0x3FFFFFu);
            unsigned int cn  = (unsigned int)(k >> 22);

            float4 r0, r1, r2, r3;
            if (tie == 0) {
                const float4* D = reinterpret_cast<const float4*>(g_diag + (size_t)u * 16);
                r0 = D[0]; r1 = D[1]; r2 = D[2]; r3 = D[3];
            } else {
                size_t eidx = (tie <= (unsigned int)E) ? (size_t)(tie - 1)
                                                       : (size_t)(tie - 1 - E);
                const float4* C = reinterpret_cast<const float4*>(g_triu + eidx * 16);
                float4 c0 = C[0], c1 = C[1], c2 = C[2], c3 = C[3];
                if (tie <= (unsigned int)E) {
                    r0 = make_float4(-c0.x, -c0.y, -c0.z, -c0.w);
                    r1 = make_float4(-c1.x, -c1.y, -c1.z, -c1.w);
                    r2 = make_float4(-c2.x, -c2.y, -c2.z, -c2.w);
                    r3 = make_float4(-c3.x, -c3.y, -c3.z, -c3.w);
                } else {                       // register transpose
                    r0 = make_float4(-c0.x, -c1.x, -c2.x, -c3.x);
                    r1 = make_float4(-c0.y, -c1.y, -c2.y, -c3.y);
                    r2 = make_float4(-c0.z, -c1.z, -c2.z, -c3.z);
                    r3 = make_float4(-c0.w, -c1.w, -c2.w, -c3.w);
                }
            }

            float cbase = (float)(cn * 4);
            float4 colv = make_float4(cbase, cbase + 1.0f, cbase + 2.0f, cbase + 3.0f);
            float rbase = (float)(u * 4);

            long long o0 = b4 + p;
            long long o1 = o0 + m;
            long long o2 = o1 + m;
            long long o3 = o2 + m;
            rows4[o0] = make_float4(rbase, rbase, rbase, rbase);
            rows4[o1] = make_float4(rbase + 1.0f, rbase + 1.0f, rbase + 1.0f, rbase + 1.0f);
            rows4[o2] = make_float4(rbase + 2.0f, rbase + 2.0f, rbase + 2.0f, rbase + 2.0f);
            rows4[o3] = make_float4(rbase + 3.0f, rbase + 3.0f, rbase + 3.0f, rbase + 3.0f);
            cols4[o0] = colv; cols4[o1] = colv; cols4[o2] = colv; cols4[o3] = colv;
            vals4[o0] = r0;   vals4[o1] = r1;   vals4[o2] = r2;   vals4[o3] = r3;
        }
    } else {
        // -------- tie path: scalar, column-major run interleave --------
        int m4 = m * 4;
#pragma unroll
        for (int a = 0; a < 4; a++) {
            float rowv = (float)(u * 4 + a);
            long long rbase = base + (long long)a * m4;
            for (int i = lane; i < m4; i += 32) {
                int p0 = i >> 2;
                unsigned int cn0 = (unsigned int)(skey[w][p0] >> 22);
                int s = p0, t = p0;
                while (s > 0 && (unsigned int)(skey[w][s - 1] >> 22) == cn0) s--;
                while (t + 1 < m && (unsigned int)(skey[w][t + 1] >> 22) == cn0) t++;
                int L = t - s + 1;
                int p, b;
                if (L == 1) { p = p0; b = i & 3; }
                else        { int j = i - 4 * s; b = j / L; p = s + j % L; }

                unsigned long long k = skey[w][p];
                unsigned int tie = (unsigned int)(k & 0x3FFFFFu);
                unsigned int cn  = (unsigned int)(k >> 22);

                float v;
                if (tie == 0)
                    v = g_diag[(size_t)u * 16 + a * 4 + b];
                else if (tie <= (unsigned int)E)
                    v = -g_triu[(size_t)(tie - 1) * 16 + a * 4 + b];
                else
                    v = -g_triu[(size_t)(tie - 1 - E) * 16 + b * 4 + a];

                long long o = rbase + i;
                rows[o] = rowv;
                cols[o] = (float)(cn * 4 + b);
                vals[o] = v;
            }
        }
    }
}

// ---------------------------------------------------------------------------
// Launch (kernel launches + CUB scan only — graph-capturable).
// ---------------------------------------------------------------------------
extern "C" void kernel_launch(void* const* d_in, const int* in_sizes, int n_in,
                              void* d_out, int out_size)
{
    const float* maps = (const float*)d_in[0];
    const int*   ei   = (const int*)d_in[1];

    const long long mapsN = (long long)in_sizes[0];   // 2E * 16
    const int twoE = (int)(mapsN / 16);
    const int E = twoE / 2;
    const long long T = (long long)out_size / 3;
    const int n = (int)((T - (long long)E * 32) / 16);

    void *cnt_p, *off_p, *tmp_p;
    cudaGetSymbolAddress(&cnt_p, g_cnt);
    cudaGetSymbolAddress(&off_p, g_off);
    cudaGetSymbolAddress(&tmp_p, g_scan_tmp);

    const int tB = 256;

    k_init<<<(n * 16 + tB - 1) / tB, tB>>>(n);
    k_edge<<<(twoE + tB - 1) / tB, tB>>>(maps, ei, E, twoE);

    // offsets = exclusive_sum(counts) over n+1 slots (off[n] = total items)
    size_t tmp_bytes = SCAN_TMP_BYTES;
    cub::DeviceScan::ExclusiveSum(tmp_p, tmp_bytes,
                                  (const int*)cnt_p, (int*)off_p, n + 1);

    k_scatter<<<(n + E + tB - 1) / tB, tB>>>(ei, n, E, twoE);

    int seBlocks = (n + SE_WARPS - 1) / SE_WARPS;
    k_sort_emit<<<seBlocks, SE_WARPS * 32>>>((float*)d_out, n, E, T);
}

// round 17
// speedup vs baseline: 6.8697x; 1.1896x over previous
#include <cuda_runtime.h>
#include <cub/cub.cuh>
#include <cstdint>
#include <cstddef>

// ---------------------------------------------------------------------------
// Shapes: n = 50,000 nodes, E = 800,000 (2E = 1.6M maps), T = 26.4M entries.
// Items (per-node incident list): n + 2E = 1.65M.
// ---------------------------------------------------------------------------
static constexpr int    MAX_N = 65536;
static constexpr size_t MAX_E = 1u << 20;            // >= 800,000
static constexpr size_t MAX_I = 1u << 21;            // >= n + 2E = 1.65M
static constexpr size_t SCAN_TMP_BYTES = 4u << 20;

static constexpr int SORT_CAP = 256;   // max items per node (Poisson(33) tail: ~0)

__device__ float              g_diag[MAX_N * 16];       //  4 MB
__device__ float              g_triu[MAX_E * 16];       // 64 MB  (A^T B, row-major)
__device__ unsigned long long g_items[MAX_I];           // 16 MB  (bucketed keys)
__device__ int                g_cnt[MAX_N + 1];
__device__ int                g_off[MAX_N + 1];
__device__ int                g_cur[MAX_N];
__device__ unsigned char      g_scan_tmp[SCAN_TMP_BYTES];

// ---------------------------------------------------------------------------
// Zero/seed accumulators (graph replays re-run atomics).
// cnt[u] starts at 1: the diag item of every node.
// ---------------------------------------------------------------------------
__global__ void k_init(int n)
{
    int i = blockIdx.x * blockDim.x + threadIdx.x;
    int n16 = n * 16;
    if (i < n16) g_diag[i] = 0.0f;
    if (i < n)  { g_cnt[i] = 1; g_cur[i] = 0; }
    if (i == n)  g_cnt[n] = 0;
}

// ---------------------------------------------------------------------------
// Count edge incidences (light pass; only reads ei).
// ---------------------------------------------------------------------------
__global__ void k_count(const int* __restrict__ ei, int E, int twoE)
{
    int e = blockIdx.x * blockDim.x + threadIdx.x;
    if (e >= E) return;
    atomicAdd(&g_cnt[ei[e]], 1);             // ij item at row node
    atomicAdd(&g_cnt[ei[twoE + e]], 1);      // ji item at col node
}

// ---------------------------------------------------------------------------
// Per-edge 4x4 products + item scatter (offsets ready after the scan).
//   e in [0,2E): S = A_e^T A_e atomically added into g_diag[ei[e]] (vec4 RED).
//   e in [0,E):  g_triu[e] = A_e^T A_{E+e}; scatter ij/ji items.
//   e in [0,n):  scatter the diag item of node e (tie = 0).
// key = (col_node << 22) | tiekey; tiekey: 0 diag, 1+e ij, 1+E+e ji.
// Bucket order is arbitrary (atomics); keys are unique per node, so the
// per-node sort is deterministic and reproduces the reference's stable
// lexsort tie-breaking (tiekey == concatenation order).
// ---------------------------------------------------------------------------
__global__ void k_edge(const float* __restrict__ maps,
                       const int* __restrict__ ei,
                       int n, int E, int twoE)
{
    int e = blockIdx.x * blockDim.x + threadIdx.x;
    if (e >= twoE) return;

    if (e < n) {   // diag item scatter (any thread order is fine)
        int pos = g_off[e] + atomicAdd(&g_cur[e], 1);
        g_items[pos] = ((unsigned long long)e << 22);
    }

    const float4* Ap = reinterpret_cast<const float4*>(maps + (size_t)e * 16);
    float Am[4][4];
#pragma unroll
    for (int r = 0; r < 4; r++) {
        float4 q = Ap[r];
        Am[r][0] = q.x; Am[r][1] = q.y; Am[r][2] = q.z; Am[r][3] = q.w;
    }

    int node = ei[e];
    float* dst = g_diag + (size_t)node * 16;
#pragma unroll
    for (int b = 0; b < 4; b++) {
        float s0 = Am[0][b] * Am[0][0] + Am[1][b] * Am[1][0] + Am[2][b] * Am[2][0] + Am[3][b] * Am[3][0];
        float s1 = Am[0][b] * Am[0][1] + Am[1][b] * Am[1][1] + Am[2][b] * Am[2][1] + Am[3][b] * Am[3][1];
        float s2 = Am[0][b] * Am[0][2] + Am[1][b] * Am[1][2] + Am[2][b] * Am[2][2] + Am[3][b] * Am[3][2];
        float s3 = Am[0][b] * Am[0][3] + Am[1][b] * Am[1][3] + Am[2][b] * Am[2][3] + Am[3][b] * Am[3][3];
#if defined(__CUDA_ARCH__) && (__CUDA_ARCH__ >= 900)
        atomicAdd(reinterpret_cast<float4*>(dst) + b, make_float4(s0, s1, s2, s3));
#else
        atomicAdd(dst + b * 4 + 0, s0);
        atomicAdd(dst + b * 4 + 1, s1);
        atomicAdd(dst + b * 4 + 2, s2);
        atomicAdd(dst + b * 4 + 3, s3);
#endif
    }

    if (e < E) {
        const float4* Bp = reinterpret_cast<const float4*>(maps + (size_t)(E + e) * 16);
        float Bm[4][4];
#pragma unroll
        for (int r = 0; r < 4; r++) {
            float4 q = Bp[r];
            Bm[r][0] = q.x; Bm[r][1] = q.y; Bm[r][2] = q.z; Bm[r][3] = q.w;
        }
        float4* tri = reinterpret_cast<float4*>(g_triu + (size_t)e * 16);
#pragma unroll
        for (int b = 0; b < 4; b++) {
            float4 o;
            o.x = Am[0][b] * Bm[0][0] + Am[1][b] * Bm[1][0] + Am[2][b] * Bm[2][0] + Am[3][b] * Bm[3][0];
            o.y = Am[0][b] * Bm[0][1] + Am[1][b] * Bm[1][1] + Am[2][b] * Bm[2][1] + Am[3][b] * Bm[3][1];
            o.z = Am[0][b] * Bm[0][2] + Am[1][b] * Bm[1][2] + Am[2][b] * Bm[2][2] + Am[3][b] * Bm[3][2];
            o.w = Am[0][b] * Bm[0][3] + Am[1][b] * Bm[1][3] + Am[2][b] * Bm[2][3] + Am[3][b] * Bm[3][3];
            tri[b] = o;
        }
        int v = ei[twoE + e];
        int p1 = g_off[node] + atomicAdd(&g_cur[node], 1);
        g_items[p1] = ((unsigned long long)v << 22) | (unsigned long long)(1 + e);
        int p2 = g_off[v] + atomicAdd(&g_cur[v], 1);
        g_items[p2] = ((unsigned long long)node << 22) | (unsigned long long)(1 + E + e);
    }
}

// ---------------------------------------------------------------------------
// Fused per-node RANK SORT + expansion + emit.  One warp per node.
//   - rank sort: keys unique => rank = #(smaller keys). One O(m) pass of
//     broadcast smem reads per lane-item; 3 syncwarps total. ~5x fewer ops
//     than the bitonic network it replaces.
//   - FAST PATH (no equal-col-node runs, ~99% of nodes): item-major — each
//     lane owns one item, loads its full 64 B value block once, register-
//     transposes for ji items, writes 12 float4s via streaming stores.
//   - TIE PATH: scalar expansion with column-major run interleave
//     (reference tie semantics), transposed indexing into g_triu for ji.
// ---------------------------------------------------------------------------
static constexpr int SE_WARPS = 8;

__global__ __launch_bounds__(SE_WARPS * 32)
void k_sort_emit(float* __restrict__ out, int n, int E, long long T)
{
    __shared__ unsigned long long skey[SE_WARPS][SORT_CAP];

    int w    = threadIdx.x >> 5;
    int lane = threadIdx.x & 31;
    int u    = blockIdx.x * SE_WARPS + w;
    if (u >= n) return;

    int beg = g_off[u];
    int m   = g_off[u + 1] - beg;            // >= 1 (diag always present)

    // ---- load keys (registers + smem) ----
    unsigned long long kreg[(SORT_CAP + 31) / 32];
    int nk = 0;
    for (int i = lane; i < m; i += 32) {
        unsigned long long k = g_items[beg + i];
        skey[w][i] = k;
        kreg[nk++] = k;
    }
    __syncwarp();

    // ---- rank sort (keys unique within a node) ----
    int rreg[(SORT_CAP + 31) / 32];
    for (int c = 0; c < nk; c++) {
        unsigned long long k = kreg[c];
        int r = 0;
        for (int j = 0; j < m; j++)          // broadcast reads, conflict-free
            r += (skey[w][j] < k);
        rreg[c] = r;
    }
    __syncwarp();                            // all reads done before overwrite
    for (int c = 0; c < nk; c++)
        skey[w][rreg[c]] = kreg[c];
    __syncwarp();

    // ---- any equal-col-node runs? ----
    bool mytie = false;
    for (int p = lane; p < m; p += 32)
        if (p > 0 && (skey[w][p] >> 22) == (skey[w][p - 1] >> 22)) mytie = true;
    bool has_tie = __any_sync(0xffffffffu, mytie);

    long long base = (long long)beg * 16;    // element offset of this node's block
    float* rows = out;
    float* cols = out + T;
    float* vals = out + 2 * T;

    if (!has_tie) {
        // -------- fast path: item-major, one 64 B value load per item --------
        long long b4 = base >> 2;            // float4 index of node block start
        float4* rows4 = reinterpret_cast<float4*>(rows);
        float4* cols4 = reinterpret_cast<float4*>(cols);
        float4* vals4 = reinterpret_cast<float4*>(vals);

        for (int p = lane; p < m; p += 32) {
            unsigned long long k = skey[w][p];
            unsigned int tie = (unsigned int)(k & 0x3FFFFFu);
            unsigned int cn  = (unsigned int)(k >> 22);

            float4 r0, r1, r2, r3;
            if (tie == 0) {
                const float4* D = reinterpret_cast<const float4*>(g_diag + (size_t)u * 16);
                r0 = D[0]; r1 = D[1]; r2 = D[2]; r3 = D[3];
            } else {
                size_t eidx = (tie <= (unsigned int)E) ? (size_t)(tie - 1)
                                                       : (size_t)(tie - 1 - E);
                const float4* C = reinterpret_cast<const float4*>(g_triu + eidx * 16);
                float4 c0 = C[0], c1 = C[1], c2 = C[2], c3 = C[3];
                if (tie <= (unsigned int)E) {
                    r0 = make_float4(-c0.x, -c0.y, -c0.z, -c0.w);
                    r1 = make_float4(-c1.x, -c1.y, -c1.z, -c1.w);
                    r2 = make_float4(-c2.x, -c2.y, -c2.z, -c2.w);
                    r3 = make_float4(-c3.x, -c3.y, -c3.z, -c3.w);
                } else {                       // register transpose
                    r0 = make_float4(-c0.x, -c1.x, -c2.x, -c3.x);
                    r1 = make_float4(-c0.y, -c1.y, -c2.y, -c3.y);
                    r2 = make_float4(-c0.z, -c1.z, -c2.z, -c3.z);
                    r3 = make_float4(-c0.w, -c1.w, -c2.w, -c3.w);
                }
            }

            float cbase = (float)(cn * 4);
            float4 colv = make_float4(cbase, cbase + 1.0f, cbase + 2.0f, cbase + 3.0f);
            float rbase = (float)(u * 4);

            long long o0 = b4 + p;
            long long o1 = o0 + m;
            long long o2 = o1 + m;
            long long o3 = o2 + m;
            __stcs(&rows4[o0], make_float4(rbase, rbase, rbase, rbase));
            __stcs(&rows4[o1], make_float4(rbase + 1.0f, rbase + 1.0f, rbase + 1.0f, rbase + 1.0f));
            __stcs(&rows4[o2], make_float4(rbase + 2.0f, rbase + 2.0f, rbase + 2.0f, rbase + 2.0f));
            __stcs(&rows4[o3], make_float4(rbase + 3.0f, rbase + 3.0f, rbase + 3.0f, rbase + 3.0f));
            __stcs(&cols4[o0], colv);
            __stcs(&cols4[o1], colv);
            __stcs(&cols4[o2], colv);
            __stcs(&cols4[o3], colv);
            __stcs(&vals4[o0], r0);
            __stcs(&vals4[o1], r1);
            __stcs(&vals4[o2], r2);
            __stcs(&vals4[o3], r3);
        }
    } else {
        // -------- tie path: scalar, column-major run interleave --------
        int m4 = m * 4;
#pragma unroll
        for (int a = 0; a < 4; a++) {
            float rowv = (float)(u * 4 + a);
            long long rbase = base + (long long)a * m4;
            for (int i = lane; i < m4; i += 32) {
                int p0 = i >> 2;
                unsigned int cn0 = (unsigned int)(skey[w][p0] >> 22);
                int s = p0, t = p0;
                while (s > 0 && (unsigned int)(skey[w][s - 1] >> 22) == cn0) s--;
                while (t + 1 < m && (unsigned int)(skey[w][t + 1] >> 22) == cn0) t++;
                int L = t - s + 1;
                int p, b;
                if (L == 1) { p = p0; b = i & 3; }
                else        { int j = i - 4 * s; b = j / L; p = s + j % L; }

                unsigned long long k = skey[w][p];
                unsigned int tie = (unsigned int)(k & 0x3FFFFFu);
                unsigned int cn  = (unsigned int)(k >> 22);

                float v;
                if (tie == 0)
                    v = g_diag[(size_t)u * 16 + a * 4 + b];
                else if (tie <= (unsigned int)E)
                    v = -g_triu[(size_t)(tie - 1) * 16 + a * 4 + b];
                else
                    v = -g_triu[(size_t)(tie - 1 - E) * 16 + b * 4 + a];

                long long o = rbase + i;
                rows[o] = rowv;
                cols[o] = (float)(cn * 4 + b);
                vals[o] = v;
            }
        }
    }
}

// ---------------------------------------------------------------------------
// Launch (kernel launches + CUB scan only — graph-capturable).
// ---------------------------------------------------------------------------
extern "C" void kernel_launch(void* const* d_in, const int* in_sizes, int n_in,
                              void* d_out, int out_size)
{
    const float* maps = (const float*)d_in[0];
    const int*   ei   = (const int*)d_in[1];

    const long long mapsN = (long long)in_sizes[0];   // 2E * 16
    const int twoE = (int)(mapsN / 16);
    const int E = twoE / 2;
    const long long T = (long long)out_size / 3;
    const int n = (int)((T - (long long)E * 32) / 16);

    void *cnt_p, *off_p, *tmp_p;
    cudaGetSymbolAddress(&cnt_p, g_cnt);
    cudaGetSymbolAddress(&off_p, g_off);
    cudaGetSymbolAddress(&tmp_p, g_scan_tmp);

    const int tB = 256;

    k_init<<<(n * 16 + tB - 1) / tB, tB>>>(n);
    k_count<<<(E + tB - 1) / tB, tB>>>(ei, E, twoE);

    // offsets = exclusive_sum(counts) over n+1 slots (off[n] = total items)
    size_t tmp_bytes = SCAN_TMP_BYTES;
    cub::DeviceScan::ExclusiveSum(tmp_p, tmp_bytes,
                                  (const int*)cnt_p, (int*)off_p, n + 1);

    k_edge<<<(twoE + tB - 1) / tB, tB>>>(maps, ei, n, E, twoE);

    int seBlocks = (n + SE_WARPS - 1) / SE_WARPS;
    k_sort_emit<<<seBlocks, SE_WARPS * 32>>>((float*)d_out, n, E, T);
}